// round 2
// baseline (speedup 1.0000x reference)
#include <cuda_runtime.h>
#include <math.h>

#define BB 8
#define TT 2048
#define CC 1024
#define HH 128

// Scratch for projected q, k, v (fp32). 3 x 8.4 MB static device arrays.
__device__ float g_q[BB * TT * HH];
__device__ float g_k[BB * TT * HH];
__device__ float g_v[BB * TT * HH];

// ---------------------------------------------------------------------------
// Kernel 1: QKV projection.  out = x @ W  with x:[B*T, C], W:[C, H].
// Block tile: 64 rows x 128 cols (full H). Threads: 256 (16x16),
// per-thread register tile 4x8. K tiled by 32 with transposed-x smem so
// fragment loads are LDS.128.
// ---------------------------------------------------------------------------
#define GM 64
#define GK 32
#define XS_STRIDE (GM + 4)   // 68 floats -> 272B rows, 16B aligned

__global__ __launch_bounds__(256) void qkv_kernel(
    const float* __restrict__ x,
    const float* __restrict__ Wk,
    const float* __restrict__ Wq,
    const float* __restrict__ Wv)
{
    __shared__ __align__(16) float xs[GK][XS_STRIDE];
    __shared__ __align__(16) float ws[GK][HH];

    const float* W   = (blockIdx.y == 0) ? Wk : (blockIdx.y == 1 ? Wq : Wv);
    float*       out = (blockIdx.y == 0) ? g_k : (blockIdx.y == 1 ? g_q : g_v);

    const int tid   = threadIdx.x;
    const int m_idx = tid >> 4;   // 0..15
    const int n_idx = tid & 15;   // 0..15
    const int row0  = blockIdx.x * GM;

    float acc[4][8];
#pragma unroll
    for (int r = 0; r < 4; r++)
#pragma unroll
        for (int c = 0; c < 8; c++) acc[r][c] = 0.0f;

    for (int k0 = 0; k0 < CC; k0 += GK) {
        // Load x tile 64x32 (transposed into smem).
#pragma unroll
        for (int l = 0; l < 2; l++) {
            int idx = tid * 2 + l;           // 0..511 float4
            int row = idx >> 3;              // 0..63
            int kq  = idx & 7;               // float4 within the 32-wide k slab
            float4 v = *(const float4*)&x[(size_t)(row0 + row) * CC + k0 + kq * 4];
            xs[kq * 4 + 0][row] = v.x;
            xs[kq * 4 + 1][row] = v.y;
            xs[kq * 4 + 2][row] = v.z;
            xs[kq * 4 + 3][row] = v.w;
        }
        // Load W tile 32x128 (row-major).
#pragma unroll
        for (int l = 0; l < 4; l++) {
            int idx = tid * 4 + l;           // 0..1023 float4
            int row = idx >> 5;              // 0..31
            int c4  = idx & 31;              // 0..31
            *(float4*)&ws[row][c4 * 4] =
                *(const float4*)&W[(size_t)(k0 + row) * HH + c4 * 4];
        }
        __syncthreads();

#pragma unroll 8
        for (int kk = 0; kk < GK; kk++) {
            float4 a  = *(const float4*)&xs[kk][m_idx * 4];
            float4 b0 = *(const float4*)&ws[kk][n_idx * 8];
            float4 b1 = *(const float4*)&ws[kk][n_idx * 8 + 4];
            float av[4] = {a.x, a.y, a.z, a.w};
            float bv[8] = {b0.x, b0.y, b0.z, b0.w, b1.x, b1.y, b1.z, b1.w};
#pragma unroll
            for (int r = 0; r < 4; r++)
#pragma unroll
                for (int c = 0; c < 8; c++)
                    acc[r][c] += av[r] * bv[c];
        }
        __syncthreads();
    }

#pragma unroll
    for (int r = 0; r < 4; r++) {
        float4 w0 = {acc[r][0], acc[r][1], acc[r][2], acc[r][3]};
        float4 w1 = {acc[r][4], acc[r][5], acc[r][6], acc[r][7]};
        size_t o = (size_t)(row0 + m_idx * 4 + r) * HH + n_idx * 8;
        *(float4*)&out[o]     = w0;
        *(float4*)&out[o + 4] = w1;
    }
}

// ---------------------------------------------------------------------------
// Kernel 2: causal flash attention.
// One block = (batch b, query tile of 64 rows). Loop over key tiles of 64.
// Smem: Qs [128][68] (d-major, transposed), Ks [128][68], Vs [64][128],
//       Ps [64][68] (n-major, transposed).  Total 119808 B dynamic smem.
// Threads: 256 (16x16). S fragment 4x4 per thread, O fragment 4x8.
// ---------------------------------------------------------------------------
#define FM 64
#define FN 64
#define FD 128
#define TS 68                       // transposed-tile row stride (floats)
#define QS_OFF 0
#define KS_OFF (FD * TS)            // 8704
#define VS_OFF (2 * FD * TS)        // 17408
#define PS_OFF (2 * FD * TS + FN * FD)  // 25600
#define SMEM_FLOATS (PS_OFF + FN * TS)  // 29952
#define SMEM_BYTES (SMEM_FLOATS * 4)    // 119808

__global__ __launch_bounds__(256) void attn_kernel(float* __restrict__ out)
{
    extern __shared__ __align__(16) float smem[];
    float* Qs = smem + QS_OFF;
    float* Ks = smem + KS_OFF;
    float* Vs = smem + VS_OFF;
    float* Ps = smem + PS_OFF;

    const int b  = blockIdx.y;
    const int qt = (gridDim.x - 1) - blockIdx.x;  // long blocks first
    const int tid   = threadIdx.x;
    const int m_idx = tid >> 4;
    const int n_idx = tid & 15;
    const float scale = 0.08838834764831845f;     // 128^-0.5

    // Load + transpose + scale Q tile: 64 x 128.
    const float* qg = g_q + ((size_t)b * TT + qt * FM) * HH;
#pragma unroll
    for (int l = 0; l < 8; l++) {
        int idx = l * 256 + tid;     // 0..2047 float4
        int row = idx >> 5;          // 0..63
        int c4  = idx & 31;          // 0..31
        float4 v = *(const float4*)&qg[(size_t)row * HH + c4 * 4];
        Qs[(c4 * 4 + 0) * TS + row] = v.x * scale;
        Qs[(c4 * 4 + 1) * TS + row] = v.y * scale;
        Qs[(c4 * 4 + 2) * TS + row] = v.z * scale;
        Qs[(c4 * 4 + 3) * TS + row] = v.w * scale;
    }

    float m_i[4], l_i[4], o[4][8];
#pragma unroll
    for (int r = 0; r < 4; r++) {
        m_i[r] = -1e30f;
        l_i[r] = 0.0f;
#pragma unroll
        for (int c = 0; c < 8; c++) o[r][c] = 0.0f;
    }

    const float* kg = g_k + (size_t)b * TT * HH;
    const float* vg = g_v + (size_t)b * TT * HH;

    for (int j = 0; j <= qt; j++) {
        // Load K tile (transposed) and V tile (row-major).
#pragma unroll
        for (int l = 0; l < 8; l++) {
            int idx = l * 256 + tid;
            int row = idx >> 5;
            int c4  = idx & 31;
            float4 kv = *(const float4*)&kg[(size_t)(j * FN + row) * HH + c4 * 4];
            Ks[(c4 * 4 + 0) * TS + row] = kv.x;
            Ks[(c4 * 4 + 1) * TS + row] = kv.y;
            Ks[(c4 * 4 + 2) * TS + row] = kv.z;
            Ks[(c4 * 4 + 3) * TS + row] = kv.w;
            float4 vv = *(const float4*)&vg[(size_t)(j * FN + row) * HH + c4 * 4];
            *(float4*)&Vs[row * FD + c4 * 4] = vv;
        }
        __syncthreads();

        // S = Q K^T  (4x4 fragment)
        float s[4][4];
#pragma unroll
        for (int r = 0; r < 4; r++)
#pragma unroll
            for (int c = 0; c < 4; c++) s[r][c] = 0.0f;

#pragma unroll 8
        for (int kk = 0; kk < FD; kk++) {
            float4 a  = *(const float4*)&Qs[kk * TS + m_idx * 4];
            float4 bb = *(const float4*)&Ks[kk * TS + n_idx * 4];
            float av[4] = {a.x, a.y, a.z, a.w};
            float bv[4] = {bb.x, bb.y, bb.z, bb.w};
#pragma unroll
            for (int r = 0; r < 4; r++)
#pragma unroll
                for (int c = 0; c < 4; c++)
                    s[r][c] += av[r] * bv[c];
        }

        // Causal mask (only the diagonal tile needs it).
        if (j == qt) {
#pragma unroll
            for (int r = 0; r < 4; r++)
#pragma unroll
                for (int c = 0; c < 4; c++)
                    if (n_idx * 4 + c > m_idx * 4 + r) s[r][c] = -1e30f;
        }

        // Online softmax per owned row; row group = 16 lanes (same m_idx).
#pragma unroll
        for (int r = 0; r < 4; r++) {
            float mx = fmaxf(fmaxf(s[r][0], s[r][1]), fmaxf(s[r][2], s[r][3]));
#pragma unroll
            for (int off = 8; off >= 1; off >>= 1)
                mx = fmaxf(mx, __shfl_xor_sync(0xffffffffu, mx, off, 16));
            float mnew = fmaxf(m_i[r], mx);
            float corr = __expf(m_i[r] - mnew);
            float ls = 0.0f;
#pragma unroll
            for (int c = 0; c < 4; c++) {
                float p = __expf(s[r][c] - mnew);
                s[r][c] = p;
                ls += p;
            }
#pragma unroll
            for (int off = 8; off >= 1; off >>= 1)
                ls += __shfl_xor_sync(0xffffffffu, ls, off, 16);
            l_i[r] = l_i[r] * corr + ls;
            m_i[r] = mnew;
#pragma unroll
            for (int c = 0; c < 8; c++) o[r][c] *= corr;
            // Stage P transposed: Ps[n][m]
#pragma unroll
            for (int c = 0; c < 4; c++)
                Ps[(n_idx * 4 + c) * TS + m_idx * 4 + r] = s[r][c];
        }
        __syncthreads();

        // O += P V   (4x8 fragment, inner loop over the 64 keys)
#pragma unroll 4
        for (int n = 0; n < FN; n++) {
            float4 a  = *(const float4*)&Ps[n * TS + m_idx * 4];
            float4 b0 = *(const float4*)&Vs[n * FD + n_idx * 8];
            float4 b1 = *(const float4*)&Vs[n * FD + n_idx * 8 + 4];
            float av[4] = {a.x, a.y, a.z, a.w};
            float bv[8] = {b0.x, b0.y, b0.z, b0.w, b1.x, b1.y, b1.z, b1.w};
#pragma unroll
            for (int r = 0; r < 4; r++)
#pragma unroll
                for (int c = 0; c < 8; c++)
                    o[r][c] += av[r] * bv[c];
        }
        __syncthreads();
    }

    // Epilogue: normalize and store.
    float* og = out + ((size_t)b * TT + qt * FM) * HH;
#pragma unroll
    for (int r = 0; r < 4; r++) {
        float inv = 1.0f / l_i[r];
        float4 w0 = {o[r][0] * inv, o[r][1] * inv, o[r][2] * inv, o[r][3] * inv};
        float4 w1 = {o[r][4] * inv, o[r][5] * inv, o[r][6] * inv, o[r][7] * inv};
        size_t off = (size_t)(m_idx * 4 + r) * HH + n_idx * 8;
        *(float4*)&og[off]     = w0;
        *(float4*)&og[off + 4] = w1;
    }
}

// ---------------------------------------------------------------------------
extern "C" void kernel_launch(void* const* d_in, const int* in_sizes, int n_in,
                              void* d_out, int out_size)
{
    const float* x  = (const float*)d_in[0];
    const float* Wk = (const float*)d_in[1];
    const float* Wq = (const float*)d_in[2];
    const float* Wv = (const float*)d_in[3];
    float* out = (float*)d_out;

    // Idempotent; executes immediately (not a stream op), capture-safe.
    cudaFuncSetAttribute(attn_kernel,
                         cudaFuncAttributeMaxDynamicSharedMemorySize, SMEM_BYTES);

    dim3 gq((BB * TT) / GM, 3);
    qkv_kernel<<<gq, 256>>>(x, Wk, Wq, Wv);

    dim3 ga(TT / FM, BB);
    attn_kernel<<<ga, 256, SMEM_BYTES>>>(out);
}

// round 5
// speedup vs baseline: 2.6357x; 2.6357x over previous
#include <cuda_runtime.h>
#include <cstdint>

#define BB 8
#define TT 2048
#define CC 1024
#define HH 128
#define NTOK (BB * TT)
#define NQT  (TT / 128)

// scale * log2(e): softmax done in base 2, scale folded into q at projection
#define QSCALE (0.08838834764831845f * 1.4426950408889634f)

__device__ float g_q[NTOK * HH];
__device__ float g_k[NTOK * HH];
__device__ float g_v[NTOK * HH];

static __device__ __forceinline__ uint32_t f2tf(float f) {
    uint32_t r; asm("cvt.rna.tf32.f32 %0, %1;" : "=r"(r) : "f"(f)); return r;
}
static __device__ __forceinline__ float ex2f(float x) {
    float r; asm("ex2.approx.f32 %0, %1;" : "=f"(r) : "f"(x)); return r;
}
// D += A*B, m16n8k8 tf32
static __device__ __forceinline__ void mma8(float* d, const uint32_t* a,
                                            uint32_t b0, uint32_t b1) {
    asm volatile(
        "mma.sync.aligned.m16n8k8.row.col.f32.tf32.tf32.f32 "
        "{%0,%1,%2,%3}, {%4,%5,%6,%7}, {%8,%9}, {%0,%1,%2,%3};"
        : "+f"(d[0]), "+f"(d[1]), "+f"(d[2]), "+f"(d[3])
        : "r"(a[0]), "r"(a[1]), "r"(a[2]), "r"(a[3]), "r"(b0), "r"(b1));
}

// ---------------------------------------------------------------------------
// Kernel 1: QKV projection. CTA = 128 tokens x 128 outs, K chunk 64.
// smem strides: xs 68 (A pattern g*s+t conflict-free), ws 136 (B pattern t*s+g).
// ---------------------------------------------------------------------------
#define XS_STR 68
#define WS_STR 136
#define QKV_SMEM_WORDS (128 * XS_STR + 64 * WS_STR)
#define QKV_SMEM_BYTES (QKV_SMEM_WORDS * 4)

__global__ __launch_bounds__(256, 2) void qkv_kernel(
    const float* __restrict__ x,  const float* __restrict__ Wk,
    const float* __restrict__ Wq, const float* __restrict__ Wv)
{
    extern __shared__ uint32_t sm[];
    uint32_t* xs = sm;                 // [128][68]
    uint32_t* ws = sm + 128 * XS_STR;  // [64][136]

    const int w = blockIdx.y;
    const float* W = (w == 0) ? Wk : (w == 1 ? Wq : Wv);
    float* outp    = (w == 0) ? g_k : (w == 1 ? g_q : g_v);
    const int row0 = blockIdx.x * 128;

    const int tid = threadIdx.x, lane = tid & 31, wid = tid >> 5;
    const int wm = wid >> 1, wn = wid & 1;
    const int m0 = wm * 32, n0 = wn * 64;
    const int g = lane >> 2, t = lane & 3;

    float acc[2][8][4];
#pragma unroll
    for (int ma = 0; ma < 2; ma++)
#pragma unroll
        for (int na = 0; na < 8; na++)
#pragma unroll
            for (int r = 0; r < 4; r++) acc[ma][na][r] = 0.0f;

    for (int c = 0; c < 16; c++) {
        const int k0 = c * 64;
        {   // x tile 128x64
            int row = tid >> 1, cb = (tid & 1) * 32;
            const float* src = &x[(size_t)(row0 + row) * CC + k0 + cb];
            uint32_t* dst = &xs[row * XS_STR + cb];
#pragma unroll
            for (int i = 0; i < 8; i++) {
                float4 v = *(const float4*)(src + i * 4);
                dst[i * 4 + 0] = f2tf(v.x); dst[i * 4 + 1] = f2tf(v.y);
                dst[i * 4 + 2] = f2tf(v.z); dst[i * 4 + 3] = f2tf(v.w);
            }
        }
        {   // W tile 64x128
            int row = tid >> 2, cb = (tid & 3) * 32;
            const float* src = &W[(size_t)(k0 + row) * HH + cb];
            uint32_t* dst = &ws[row * WS_STR + cb];
#pragma unroll
            for (int i = 0; i < 8; i++) {
                float4 v = *(const float4*)(src + i * 4);
                dst[i * 4 + 0] = f2tf(v.x); dst[i * 4 + 1] = f2tf(v.y);
                dst[i * 4 + 2] = f2tf(v.z); dst[i * 4 + 3] = f2tf(v.w);
            }
        }
        __syncthreads();
#pragma unroll
        for (int ka = 0; ka < 8; ka++) {
            const int kk = ka * 8;
            uint32_t a[2][4];
#pragma unroll
            for (int ma = 0; ma < 2; ma++) {
                int r = m0 + ma * 16 + g;
                a[ma][0] = xs[r * XS_STR + kk + t];
                a[ma][1] = xs[(r + 8) * XS_STR + kk + t];
                a[ma][2] = xs[r * XS_STR + kk + t + 4];
                a[ma][3] = xs[(r + 8) * XS_STR + kk + t + 4];
            }
#pragma unroll
            for (int na = 0; na < 8; na++) {
                int col = n0 + na * 8 + g;
                uint32_t b0 = ws[(kk + t) * WS_STR + col];
                uint32_t b1 = ws[(kk + t + 4) * WS_STR + col];
                mma8(acc[0][na], a[0], b0, b1);
                mma8(acc[1][na], a[1], b0, b1);
            }
        }
        __syncthreads();
    }

    const float sc = (w == 1) ? QSCALE : 1.0f;
#pragma unroll
    for (int ma = 0; ma < 2; ma++)
#pragma unroll
        for (int na = 0; na < 8; na++) {
            int r  = row0 + m0 + ma * 16 + g;
            int cc = n0 + na * 8 + 2 * t;
            float2 v0 = {acc[ma][na][0] * sc, acc[ma][na][1] * sc};
            float2 v1 = {acc[ma][na][2] * sc, acc[ma][na][3] * sc};
            *(float2*)&outp[(size_t)r * HH + cc]       = v0;
            *(float2*)&outp[(size_t)(r + 8) * HH + cc] = v1;
        }
}

// ---------------------------------------------------------------------------
// Kernel 2: causal flash attention. CTA = (b, 128-row q-tile), key tiles 64.
// ---------------------------------------------------------------------------
#define QS_STR 132
#define KS_STR 132
#define VS_STR 136
#define PS_STR 68
#define OFF_KS (128 * QS_STR)
#define OFF_VS (OFF_KS + 64 * KS_STR)
#define OFF_PS (OFF_VS + 64 * VS_STR)
#define OFF_RM (OFF_PS + 128 * PS_STR)
#define OFF_RS (OFF_RM + 256)
#define AT_SMEM_WORDS (OFF_RS + 256)
#define AT_SMEM_BYTES (AT_SMEM_WORDS * 4)

__global__ __launch_bounds__(256, 1) void attn_kernel(float* __restrict__ out)
{
    extern __shared__ uint32_t sm[];
    uint32_t* Qs = sm;
    uint32_t* Ks = sm + OFF_KS;
    uint32_t* Vs = sm + OFF_VS;
    uint32_t* Ps = sm + OFF_PS;
    float* redm  = (float*)(sm + OFF_RM);
    float* reds  = (float*)(sm + OFF_RS);

    const int b  = blockIdx.y;
    const int qt = (gridDim.x - 1) - blockIdx.x;   // long CTAs first
    const int tid = threadIdx.x, lane = tid & 31, wid = tid >> 5;
    const int wm = wid >> 1, wn = wid & 1;
    const int m0 = wm * 32;
    const int g = lane >> 2, t = lane & 3;

    // Stage Q (already scaled by QSCALE at projection)
    {
        const float* qg = g_q + ((size_t)b * TT + qt * 128) * HH;
        int row = tid >> 1, cb = (tid & 1) * 64;
        const float* src = &qg[(size_t)row * HH + cb];
        uint32_t* dst = &Qs[row * QS_STR + cb];
#pragma unroll
        for (int i = 0; i < 16; i++) {
            float4 v = *(const float4*)(src + i * 4);
            dst[i * 4 + 0] = f2tf(v.x); dst[i * 4 + 1] = f2tf(v.y);
            dst[i * 4 + 2] = f2tf(v.z); dst[i * 4 + 3] = f2tf(v.w);
        }
    }

    float oacc[2][8][4];
#pragma unroll
    for (int ma = 0; ma < 2; ma++)
#pragma unroll
        for (int na = 0; na < 8; na++)
#pragma unroll
            for (int r = 0; r < 4; r++) oacc[ma][na][r] = 0.0f;
    float m_i[2][2] = {{-1e30f, -1e30f}, {-1e30f, -1e30f}};
    float l_i[2][2] = {{0.0f, 0.0f}, {0.0f, 0.0f}};

    const float* kg = g_k + (size_t)b * TT * HH;
    const float* vg = g_v + (size_t)b * TT * HH;
    const int nj = 2 * qt + 2;

    for (int j = 0; j < nj; j++) {
        __syncthreads();   // prev O-phase done reading Vs/Ps; Q staged (iter 0)
        {   // K tile 64x128
            int row = tid >> 2, cb = (tid & 3) * 32;
            const float* src = &kg[(size_t)(j * 64 + row) * HH + cb];
            uint32_t* dst = &Ks[row * KS_STR + cb];
#pragma unroll
            for (int i = 0; i < 8; i++) {
                float4 v = *(const float4*)(src + i * 4);
                dst[i * 4 + 0] = f2tf(v.x); dst[i * 4 + 1] = f2tf(v.y);
                dst[i * 4 + 2] = f2tf(v.z); dst[i * 4 + 3] = f2tf(v.w);
            }
        }
        {   // V tile 64x128
            int row = tid >> 2, cb = (tid & 3) * 32;
            const float* src = &vg[(size_t)(j * 64 + row) * HH + cb];
            uint32_t* dst = &Vs[row * VS_STR + cb];
#pragma unroll
            for (int i = 0; i < 8; i++) {
                float4 v = *(const float4*)(src + i * 4);
                dst[i * 4 + 0] = f2tf(v.x); dst[i * 4 + 1] = f2tf(v.y);
                dst[i * 4 + 2] = f2tf(v.z); dst[i * 4 + 3] = f2tf(v.w);
            }
        }
        __syncthreads();

        // S = Q K^T : warp tile 32m x 32n
        float sacc[2][4][4];
#pragma unroll
        for (int ma = 0; ma < 2; ma++)
#pragma unroll
            for (int na = 0; na < 4; na++)
#pragma unroll
                for (int r = 0; r < 4; r++) sacc[ma][na][r] = 0.0f;
#pragma unroll
        for (int ka = 0; ka < 16; ka++) {
            const int kk = ka * 8;
            uint32_t a[2][4];
#pragma unroll
            for (int ma = 0; ma < 2; ma++) {
                int r = m0 + ma * 16 + g;
                a[ma][0] = Qs[r * QS_STR + kk + t];
                a[ma][1] = Qs[(r + 8) * QS_STR + kk + t];
                a[ma][2] = Qs[r * QS_STR + kk + t + 4];
                a[ma][3] = Qs[(r + 8) * QS_STR + kk + t + 4];
            }
#pragma unroll
            for (int na = 0; na < 4; na++) {
                int n = wn * 32 + na * 8 + g;
                uint32_t b0 = Ks[n * KS_STR + kk + t];
                uint32_t b1 = Ks[n * KS_STR + kk + t + 4];
                mma8(sacc[0][na], a[0], b0, b1);
                mma8(sacc[1][na], a[1], b0, b1);
            }
        }

        // Causal mask (tiles intersecting the diagonal)
        if (j >= 2 * qt) {
#pragma unroll
            for (int ma = 0; ma < 2; ma++) {
                int r0g = qt * 128 + m0 + ma * 16 + g;
#pragma unroll
                for (int na = 0; na < 4; na++) {
                    int cc = j * 64 + wn * 32 + na * 8 + 2 * t;
                    if (cc > r0g)         sacc[ma][na][0] = -1e30f;
                    if (cc + 1 > r0g)     sacc[ma][na][1] = -1e30f;
                    if (cc > r0g + 8)     sacc[ma][na][2] = -1e30f;
                    if (cc + 1 > r0g + 8) sacc[ma][na][3] = -1e30f;
                }
            }
        }

        // Row max (4 row slots per lane: [ma][h], row = m0+ma*16+g+8h)
#pragma unroll
        for (int ma = 0; ma < 2; ma++)
#pragma unroll
            for (int h = 0; h < 2; h++) {
                float mx = -1e30f;
#pragma unroll
                for (int na = 0; na < 4; na++)
                    mx = fmaxf(mx, fmaxf(sacc[ma][na][2 * h], sacc[ma][na][2 * h + 1]));
                mx = fmaxf(mx, __shfl_xor_sync(0xffffffffu, mx, 1));
                mx = fmaxf(mx, __shfl_xor_sync(0xffffffffu, mx, 2));
                if (t == 0) redm[wn * 128 + m0 + ma * 16 + g + 8 * h] = mx;
            }
        __syncthreads();

        float corrv[2][2];
#pragma unroll
        for (int ma = 0; ma < 2; ma++)
#pragma unroll
            for (int h = 0; h < 2; h++) {
                int row = m0 + ma * 16 + g + 8 * h;
                float mall = fmaxf(redm[row], redm[128 + row]);
                float mnew = fmaxf(m_i[ma][h], mall);
                float corr = ex2f(m_i[ma][h] - mnew);
                corrv[ma][h] = corr;
                m_i[ma][h] = mnew;
                float ls = 0.0f;
#pragma unroll
                for (int na = 0; na < 4; na++) {
                    float p0 = ex2f(sacc[ma][na][2 * h] - mnew);
                    float p1 = ex2f(sacc[ma][na][2 * h + 1] - mnew);
                    ls += p0 + p1;
                    int cc = wn * 32 + na * 8 + 2 * t;
                    Ps[row * PS_STR + cc]     = f2tf(p0);
                    Ps[row * PS_STR + cc + 1] = f2tf(p1);
                }
                ls += __shfl_xor_sync(0xffffffffu, ls, 1);
                ls += __shfl_xor_sync(0xffffffffu, ls, 2);
                if (t == 0) reds[wn * 128 + row] = ls;
#pragma unroll
                for (int na = 0; na < 8; na++) {
                    oacc[ma][na][2 * h]     *= corr;
                    oacc[ma][na][2 * h + 1] *= corr;
                }
            }
        __syncthreads();
#pragma unroll
        for (int ma = 0; ma < 2; ma++)
#pragma unroll
            for (int h = 0; h < 2; h++) {
                int row = m0 + ma * 16 + g + 8 * h;
                l_i[ma][h] = l_i[ma][h] * corrv[ma][h] + reds[row] + reds[128 + row];
            }

        // O += P V : warp tile 32m x 64n, k = 64 keys
#pragma unroll
        for (int ka = 0; ka < 8; ka++) {
            const int kk = ka * 8;
            uint32_t a[2][4];
#pragma unroll
            for (int ma = 0; ma < 2; ma++) {
                int r = m0 + ma * 16 + g;
                a[ma][0] = Ps[r * PS_STR + kk + t];
                a[ma][1] = Ps[(r + 8) * PS_STR + kk + t];
                a[ma][2] = Ps[r * PS_STR + kk + t + 4];
                a[ma][3] = Ps[(r + 8) * PS_STR + kk + t + 4];
            }
#pragma unroll
            for (int na = 0; na < 8; na++) {
                int col = wn * 64 + na * 8 + g;
                uint32_t b0 = Vs[(kk + t) * VS_STR + col];
                uint32_t b1 = Vs[(kk + t + 4) * VS_STR + col];
                mma8(oacc[0][na], a[0], b0, b1);
                mma8(oacc[1][na], a[1], b0, b1);
            }
        }
    }

    // Epilogue: normalize, store
    float* og = out + ((size_t)b * TT + qt * 128) * HH;
    float inv[2][2];
#pragma unroll
    for (int ma = 0; ma < 2; ma++)
#pragma unroll
        for (int h = 0; h < 2; h++) inv[ma][h] = 1.0f / l_i[ma][h];
#pragma unroll
    for (int ma = 0; ma < 2; ma++)
#pragma unroll
        for (int na = 0; na < 8; na++) {
            int r  = m0 + ma * 16 + g;
            int cc = wn * 64 + na * 8 + 2 * t;
            float2 v0 = {oacc[ma][na][0] * inv[ma][0], oacc[ma][na][1] * inv[ma][0]};
            float2 v1 = {oacc[ma][na][2] * inv[ma][1], oacc[ma][na][3] * inv[ma][1]};
            *(float2*)&og[(size_t)r * HH + cc]       = v0;
            *(float2*)&og[(size_t)(r + 8) * HH + cc] = v1;
        }
}

// ---------------------------------------------------------------------------
extern "C" void kernel_launch(void* const* d_in, const int* in_sizes, int n_in,
                              void* d_out, int out_size)
{
    const float* x  = (const float*)d_in[0];
    const float* Wk = (const float*)d_in[1];
    const float* Wq = (const float*)d_in[2];
    const float* Wv = (const float*)d_in[3];
    float* out = (float*)d_out;

    cudaFuncSetAttribute(qkv_kernel,
                         cudaFuncAttributeMaxDynamicSharedMemorySize, QKV_SMEM_BYTES);
    cudaFuncSetAttribute(attn_kernel,
                         cudaFuncAttributeMaxDynamicSharedMemorySize, AT_SMEM_BYTES);

    qkv_kernel<<<dim3(NTOK / 128, 3), 256, QKV_SMEM_BYTES>>>(x, Wk, Wq, Wv);
    attn_kernel<<<dim3(NQT, BB), 256, AT_SMEM_BYTES>>>(out);
}

// round 12
// speedup vs baseline: 7.7845x; 2.9535x over previous
#include <cuda_runtime.h>
#include <cuda_fp16.h>
#include <cstdint>

#define BB 8
#define TT 2048
#define CC 1024
#define HH 128
#define NTOK (BB * TT)

#define QSCALE (0.08838834764831845f * 1.4426950408889634f)

// fp16 staging of inputs / intermediates
__device__ __half g_x16[NTOK * CC];        // x as fp16 [tok][C]
__device__ __half g_wT16[3 * HH * CC];     // W^T fp16 [w][h][C]
__device__ __half g_q16[NTOK * HH];        // q (pre-scaled) [tok][h]
__device__ __half g_k16[NTOK * HH];        // k [tok][h]
__device__ __half g_vT16[HH * NTOK];       // v transposed [h][tok]

static __device__ __forceinline__ float ex2f(float x) {
    float r; asm("ex2.approx.f32 %0, %1;" : "=f"(r) : "f"(x)); return r;
}
static __device__ __forceinline__ uint32_t packh2(float lo, float hi) {
    __half2 h = __floats2half2_rn(lo, hi);
    return *reinterpret_cast<uint32_t*>(&h);
}
// D += A*B : m16n8k16 fp16 inputs, fp32 accum
static __device__ __forceinline__ void mma16(float* d, const uint32_t* a,
                                             uint32_t b0, uint32_t b1) {
    asm volatile(
        "mma.sync.aligned.m16n8k16.row.col.f32.f16.f16.f32 "
        "{%0,%1,%2,%3}, {%4,%5,%6,%7}, {%8,%9}, {%0,%1,%2,%3};"
        : "+f"(d[0]), "+f"(d[1]), "+f"(d[2]), "+f"(d[3])
        : "r"(a[0]), "r"(a[1]), "r"(a[2]), "r"(a[3]), "r"(b0), "r"(b1));
}
static __device__ __forceinline__ void cpa16(uint32_t dst, const void* src) {
    asm volatile("cp.async.cg.shared.global [%0], [%1], 16;" :: "r"(dst), "l"(src));
}
#define CP_COMMIT() asm volatile("cp.async.commit_group;" ::: "memory")
#define CP_WAIT0()  asm volatile("cp.async.wait_group 0;" ::: "memory")
#define CP_WAIT1()  asm volatile("cp.async.wait_group 1;" ::: "memory")

// ---------------------------------------------------------------------------
// Kernel A: x fp32 -> fp16
// ---------------------------------------------------------------------------
__global__ __launch_bounds__(256) void xhalf_kernel(const float* __restrict__ x)
{
    size_t base = ((size_t)blockIdx.x * 256 + threadIdx.x) * 8;
    float4 f0 = *(const float4*)&x[base];
    float4 f1 = *(const float4*)&x[base + 4];
    uint4 u;
    u.x = packh2(f0.x, f0.y); u.y = packh2(f0.z, f0.w);
    u.z = packh2(f1.x, f1.y); u.w = packh2(f1.z, f1.w);
    *(uint4*)&g_x16[base] = u;
}

// ---------------------------------------------------------------------------
// Kernel B: W [C,H] fp32 -> W^T [H,C] fp16
// ---------------------------------------------------------------------------
__global__ __launch_bounds__(256) void wtrans_kernel(
    const float* __restrict__ Wk, const float* __restrict__ Wq,
    const float* __restrict__ Wv)
{
    int gid = blockIdx.x * 256 + threadIdx.x;   // 3*128*256 threads
    int w   = gid >> 15;
    int rem = gid & 32767;
    int h   = rem >> 8;
    int c0  = (rem & 255) * 4;
    const float* W = (w == 0) ? Wk : (w == 1 ? Wq : Wv);
    float v0 = W[(size_t)(c0 + 0) * HH + h];
    float v1 = W[(size_t)(c0 + 1) * HH + h];
    float v2 = W[(size_t)(c0 + 2) * HH + h];
    float v3 = W[(size_t)(c0 + 3) * HH + h];
    uint2 u = {packh2(v0, v1), packh2(v2, v3)};
    *(uint2*)&g_wT16[(size_t)w * HH * CC + (size_t)h * CC + c0] = u;
}

// ---------------------------------------------------------------------------
// Kernel 1: QKV projection, fp16 MMA. CTA = 128 tok x 128 out, K chunks of 64,
// cp.async double-buffered. Warps: 4m x 2n (32x64 warp tile).
// smem (halves): xs[2][128][136], ws[2][128][72]  = 106496 B
// ---------------------------------------------------------------------------
#define W_XS0 0
#define W_XS1 8704
#define W_WS0 17408
#define W_WS1 22016
#define SMEM_BYTES 106496

__global__ __launch_bounds__(256, 1) void qkv_kernel()
{
    extern __shared__ char smem[];
    uint32_t* smw = (uint32_t*)smem;
    const uint32_t sbase = (uint32_t)__cvta_generic_to_shared(smem);

    const int w    = blockIdx.y;
    const int row0 = blockIdx.x * 128;
    const __half* xg = g_x16 + (size_t)row0 * CC;
    const __half* wg = g_wT16 + (size_t)w * HH * CC;

    const int tid = threadIdx.x, lane = tid & 31, wid = tid >> 5;
    const int wm = wid >> 1, wn = wid & 1;
    const int m0 = wm * 32, n0 = wn * 64;
    const int g = lane >> 2, t = lane & 3;

    float acc[2][8][4];
#pragma unroll
    for (int ma = 0; ma < 2; ma++)
#pragma unroll
        for (int na = 0; na < 8; na++)
#pragma unroll
            for (int r = 0; r < 4; r++) acc[ma][na][r] = 0.0f;

    // stage chunk 0 into buf 0
#pragma unroll
    for (int i = 0; i < 4; i++) {
        int idx = tid + i * 256;
        int row = idx >> 3, c16 = idx & 7;
        cpa16(sbase + W_XS0 * 4 + row * 272 + c16 * 16, xg + (size_t)row * CC + c16 * 8);
        cpa16(sbase + W_WS0 * 4 + row * 144 + c16 * 16, wg + (size_t)row * CC + c16 * 8);
    }
    CP_COMMIT();

    for (int c = 0; c < 16; c++) {
        if (c + 1 < 16) {
            const int k1 = (c + 1) * 64;
            const int xw = ((c + 1) & 1) ? W_XS1 : W_XS0;
            const int ww = ((c + 1) & 1) ? W_WS1 : W_WS0;
#pragma unroll
            for (int i = 0; i < 4; i++) {
                int idx = tid + i * 256;
                int row = idx >> 3, c16 = idx & 7;
                cpa16(sbase + xw * 4 + row * 272 + c16 * 16,
                      xg + (size_t)row * CC + k1 + c16 * 8);
                cpa16(sbase + ww * 4 + row * 144 + c16 * 16,
                      wg + (size_t)row * CC + k1 + c16 * 8);
            }
            CP_COMMIT();
            CP_WAIT1();
        } else {
            CP_WAIT0();
        }
        __syncthreads();
        const uint32_t* xb = smw + ((c & 1) ? W_XS1 : W_XS0);
        const uint32_t* wb = smw + ((c & 1) ? W_WS1 : W_WS0);
#pragma unroll
        for (int ka = 0; ka < 4; ka++) {
            uint32_t a[2][4];
#pragma unroll
            for (int ma = 0; ma < 2; ma++) {
                int r = m0 + ma * 16 + g;
                a[ma][0] = xb[r * 68 + ka * 8 + t];
                a[ma][1] = xb[(r + 8) * 68 + ka * 8 + t];
                a[ma][2] = xb[r * 68 + ka * 8 + t + 4];
                a[ma][3] = xb[(r + 8) * 68 + ka * 8 + t + 4];
            }
#pragma unroll
            for (int na = 0; na < 8; na++) {
                int n = n0 + na * 8 + g;
                uint32_t b0 = wb[n * 36 + ka * 8 + t];
                uint32_t b1 = wb[n * 36 + ka * 8 + t + 4];
                mma16(acc[0][na], a[0], b0, b1);
                mma16(acc[1][na], a[1], b0, b1);
            }
        }
        __syncthreads();
    }

    // Epilogue
    if (w == 2) {
        // v -> g_vT16[d][tok]
#pragma unroll
        for (int ma = 0; ma < 2; ma++)
#pragma unroll
            for (int na = 0; na < 8; na++) {
                int r  = row0 + m0 + ma * 16 + g;
                int cc = n0 + na * 8 + 2 * t;
                g_vT16[(size_t)cc * NTOK + r]           = __float2half_rn(acc[ma][na][0]);
                g_vT16[(size_t)(cc + 1) * NTOK + r]     = __float2half_rn(acc[ma][na][1]);
                g_vT16[(size_t)cc * NTOK + r + 8]       = __float2half_rn(acc[ma][na][2]);
                g_vT16[(size_t)(cc + 1) * NTOK + r + 8] = __float2half_rn(acc[ma][na][3]);
            }
    } else {
        __half* o = (w == 0) ? g_k16 : g_q16;
        const float sc = (w == 1) ? QSCALE : 1.0f;
#pragma unroll
        for (int ma = 0; ma < 2; ma++)
#pragma unroll
            for (int na = 0; na < 8; na++) {
                int r  = row0 + m0 + ma * 16 + g;
                int cc = n0 + na * 8 + 2 * t;
                *(uint32_t*)&o[(size_t)r * HH + cc] =
                    packh2(acc[ma][na][0] * sc, acc[ma][na][1] * sc);
                *(uint32_t*)&o[(size_t)(r + 8) * HH + cc] =
                    packh2(acc[ma][na][2] * sc, acc[ma][na][3] * sc);
            }
    }
}

// ---------------------------------------------------------------------------
// Kernel 2: causal flash attention, fp16 MMA, paired q-tiles.
// CTA = (pair, batch): processes q-tiles  pair  and  15-pair  (uniform work).
// 8 warps, each owns 16 rows x full 64-key tile. Warp-local softmax,
// P reused in registers as PV A-fragments. cp.async double-buffered K/V.
// smem (words): Qs 8704 | Ks[2] 4352 | Vt[2] 4608  = 106496 B
// ---------------------------------------------------------------------------
#define W_QS  0
#define W_KS0 8704
#define W_KS1 13056
#define W_VT0 17408
#define W_VT1 22016

__global__ __launch_bounds__(256, 1) void attn_kernel(float* __restrict__ out)
{
    extern __shared__ char smem[];
    uint32_t* smw = (uint32_t*)smem;
    const uint32_t sbase = (uint32_t)__cvta_generic_to_shared(smem);

    const int pair = blockIdx.x, b = blockIdx.y;
    const int tid = threadIdx.x, lane = tid & 31, wid = tid >> 5;
    const int m0 = wid * 16;
    const int g = lane >> 2, t = lane & 3;

    const __half* kg  = g_k16 + (size_t)b * TT * HH;
    const __half* vtg = g_vT16 + (size_t)b * TT;

    for (int tt = 0; tt < 2; tt++) {
        const int qt = tt ? (15 - pair) : pair;
        const int nj = 2 * qt + 2;
        const __half* qg = g_q16 + ((size_t)b * TT + qt * 128) * HH;

        __syncthreads();  // previous tile fully done before restaging Qs

        // stage Q + K/V tile 0 (one cp.async group)
#pragma unroll
        for (int i = 0; i < 8; i++) {
            int idx = tid + i * 256;
            int row = idx >> 4, c16 = idx & 15;
            cpa16(sbase + row * 272 + c16 * 16, qg + (size_t)row * HH + c16 * 8);
        }
#pragma unroll
        for (int i = 0; i < 4; i++) {
            int idx = tid + i * 256;
            int row = idx >> 4, c16 = idx & 15;
            cpa16(sbase + W_KS0 * 4 + row * 272 + c16 * 16,
                  kg + (size_t)row * HH + c16 * 8);
            int d = idx >> 3, c8 = idx & 7;
            cpa16(sbase + W_VT0 * 4 + d * 144 + c8 * 16,
                  vtg + (size_t)d * NTOK + c8 * 8);
        }
        CP_COMMIT();

        float oacc[16][4];
#pragma unroll
        for (int na = 0; na < 16; na++)
#pragma unroll
            for (int r = 0; r < 4; r++) oacc[na][r] = 0.0f;
        float m_i[2] = {-1e30f, -1e30f};
        float l_i[2] = {0.0f, 0.0f};

        for (int j = 0; j < nj; j++) {
            if (j + 1 < nj) {
                const int kw = ((j + 1) & 1) ? W_KS1 : W_KS0;
                const int vw = ((j + 1) & 1) ? W_VT1 : W_VT0;
                const __half* ks = kg + (size_t)(j + 1) * 64 * HH;
                const __half* vs = vtg + (size_t)(j + 1) * 64;
#pragma unroll
                for (int i = 0; i < 4; i++) {
                    int idx = tid + i * 256;
                    int row = idx >> 4, c16 = idx & 15;
                    cpa16(sbase + kw * 4 + row * 272 + c16 * 16,
                          ks + (size_t)row * HH + c16 * 8);
                    int d = idx >> 3, c8 = idx & 7;
                    cpa16(sbase + vw * 4 + d * 144 + c8 * 16,
                          vs + (size_t)d * NTOK + c8 * 8);
                }
                CP_COMMIT();
                CP_WAIT1();
            } else {
                CP_WAIT0();
            }
            __syncthreads();

            const uint32_t* kb = smw + ((j & 1) ? W_KS1 : W_KS0);
            const uint32_t* vb = smw + ((j & 1) ? W_VT1 : W_VT0);

            // S = Q K^T  (warp: 16 rows x 64 keys)
            float sacc[8][4];
#pragma unroll
            for (int na = 0; na < 8; na++)
#pragma unroll
                for (int r = 0; r < 4; r++) sacc[na][r] = 0.0f;
#pragma unroll
            for (int ka = 0; ka < 8; ka++) {
                uint32_t a[4];
                int r = m0 + g;
                a[0] = smw[r * 68 + ka * 8 + t];
                a[1] = smw[(r + 8) * 68 + ka * 8 + t];
                a[2] = smw[r * 68 + ka * 8 + t + 4];
                a[3] = smw[(r + 8) * 68 + ka * 8 + t + 4];
#pragma unroll
                for (int na = 0; na < 8; na++) {
                    int n = na * 8 + g;
                    uint32_t b0 = kb[n * 68 + ka * 8 + t];
                    uint32_t b1 = kb[n * 68 + ka * 8 + t + 4];
                    mma16(sacc[na], a, b0, b1);
                }
            }

            // causal mask
            if (j >= 2 * qt) {
                int r0g = qt * 128 + m0 + g;
#pragma unroll
                for (int na = 0; na < 8; na++) {
                    int cc = j * 64 + na * 8 + 2 * t;
                    if (cc > r0g)         sacc[na][0] = -1e30f;
                    if (cc + 1 > r0g)     sacc[na][1] = -1e30f;
                    if (cc > r0g + 8)     sacc[na][2] = -1e30f;
                    if (cc + 1 > r0g + 8) sacc[na][3] = -1e30f;
                }
            }

            // warp-local online softmax (rows g and g+8)
            uint32_t ph0[8], ph1[8];
            float corr[2];
#pragma unroll
            for (int h = 0; h < 2; h++) {
                const int i0 = 2 * h;   // {0,1} row g, {2,3} row g+8
                float mx = -1e30f;
#pragma unroll
                for (int na = 0; na < 8; na++)
                    mx = fmaxf(mx, fmaxf(sacc[na][i0], sacc[na][i0 + 1]));
                mx = fmaxf(mx, __shfl_xor_sync(0xffffffffu, mx, 1));
                mx = fmaxf(mx, __shfl_xor_sync(0xffffffffu, mx, 2));
                float mnew = fmaxf(m_i[h], mx);
                corr[h] = ex2f(m_i[h] - mnew);
                m_i[h] = mnew;
                float ls = 0.0f;
#pragma unroll
                for (int na = 0; na < 8; na++) {
                    float p0 = ex2f(sacc[na][i0] - mnew);
                    float p1 = ex2f(sacc[na][i0 + 1] - mnew);
                    ls += p0 + p1;
                    if (h == 0) ph0[na] = packh2(p0, p1);
                    else        ph1[na] = packh2(p0, p1);
                }
                ls += __shfl_xor_sync(0xffffffffu, ls, 1);
                ls += __shfl_xor_sync(0xffffffffu, ls, 2);
                l_i[h] = l_i[h] * corr[h] + ls;
            }
#pragma unroll
            for (int na = 0; na < 16; na++) {
                oacc[na][0] *= corr[0]; oacc[na][1] *= corr[0];
                oacc[na][2] *= corr[1]; oacc[na][3] *= corr[1];
            }

            // O += P V   (P from registers, V^T from smem)
#pragma unroll
            for (int ka = 0; ka < 4; ka++) {
                uint32_t a[4] = {ph0[2 * ka], ph1[2 * ka],
                                 ph0[2 * ka + 1], ph1[2 * ka + 1]};
#pragma unroll
                for (int na = 0; na < 16; na++) {
                    int n = na * 8 + g;
                    uint32_t b0 = vb[n * 36 + ka * 8 + t];
                    uint32_t b1 = vb[n * 36 + ka * 8 + t + 4];
                    mma16(oacc[na], a, b0, b1);
                }
            }
            __syncthreads();  // done reading this stage's buffers
        }

        // epilogue: normalize, store fp32
        float inv0 = 1.0f / l_i[0], inv1 = 1.0f / l_i[1];
        float* og = out + ((size_t)b * TT + qt * 128) * HH;
#pragma unroll
        for (int na = 0; na < 16; na++) {
            int r  = m0 + g;
            int cc = na * 8 + 2 * t;
            float2 v0 = {oacc[na][0] * inv0, oacc[na][1] * inv0};
            float2 v1 = {oacc[na][2] * inv1, oacc[na][3] * inv1};
            *(float2*)&og[(size_t)r * HH + cc]       = v0;
            *(float2*)&og[(size_t)(r + 8) * HH + cc] = v1;
        }
    }
}

// ---------------------------------------------------------------------------
extern "C" void kernel_launch(void* const* d_in, const int* in_sizes, int n_in,
                              void* d_out, int out_size)
{
    const float* x  = (const float*)d_in[0];
    const float* Wk = (const float*)d_in[1];
    const float* Wq = (const float*)d_in[2];
    const float* Wv = (const float*)d_in[3];
    float* out = (float*)d_out;

    cudaFuncSetAttribute(qkv_kernel,
                         cudaFuncAttributeMaxDynamicSharedMemorySize, SMEM_BYTES);
    cudaFuncSetAttribute(attn_kernel,
                         cudaFuncAttributeMaxDynamicSharedMemorySize, SMEM_BYTES);

    xhalf_kernel<<<NTOK * CC / (256 * 8), 256>>>(x);
    wtrans_kernel<<<3 * HH * 256 / 256, 256>>>(Wk, Wq, Wv);
    qkv_kernel<<<dim3(NTOK / 128, 3), 256, SMEM_BYTES>>>();
    attn_kernel<<<dim3(8, BB), 256, SMEM_BYTES>>>(out);
}